// round 6
// baseline (speedup 1.0000x reference)
#include <cuda_runtime.h>
#include <cuda_bf16.h>
#include <math.h>
#include <stdint.h>

#define B 2
#define P 512
#define C 21
#define REG 5
#define DET 100
#define NGRP (B*(C-1))          // 40
#define NPROP (B*P)             // 1024
#define TOT ((C-1)*P)           // 10240 per image
#define SCORE_THRESH 0.05f
#define NMS_THR 0.5f
#define BBOX_CLIP 4.135166556742356f   // log(1000/16)
#define DEG2RAD 0.017453292519943295f
#define RAD2DEG 57.29577951308232f
#define IMW_M1 1023.0f
#define IMH_M1 799.0f
#define QCAP 131072
#define SQ_CAP 4096
#define FULLM 0xffffffffu
#define CANDCAP 256
#define K4PER (TOT / P)         // 20 values per thread in last-block topk

// ---------------- device scratch ----------------
__device__ float g_pr_s[NGRP * P * 5];           // sorted proposals
__device__ float g_bx_s[NGRP * P * 4];           // sorted aabb boxes (clipped)
__device__ float g_msk[B * (C-1) * P];           // post-NMS masked scores
__device__ int   g_queue[NGRP * QCAP];           // pair-queue overflow
__device__ unsigned g_done;                      // last-block ticket (zero-init)

// ---------------- bitonic helpers (desc by value, asc by index) -------------
__device__ __forceinline__ void cmp_shfl(float& v, int& i, int tid, int j, bool dir)
{
    float ov = __shfl_xor_sync(FULLM, v, j);
    int   oi = __shfl_xor_sync(FULLM, i, j);
    bool lower = ((tid & j) == 0);
    bool before = (v > ov) || (v == ov && i < oi);
    bool lower_before = lower ? before : !before;
    if (lower_before != dir) { v = ov; i = oi; }
}

// ---------------- exact quad-quad intersection area (matches reference) -----
__device__ float inter_area(const float* __restrict__ p1x, const float* __restrict__ p1y,
                            const float* __restrict__ p2x, const float* __restrict__ p2y)
{
    float px[8], py[8];
    #pragma unroll
    for (int i = 0; i < 4; i++) { px[i] = p1x[i]; py[i] = p1y[i]; }
    int n = 4;

    for (int k = 0; k < 4; k++) {
        float ax = p2x[k], ay = p2y[k];
        int k1 = (k + 1) & 3;
        float dx = p2x[k1] - ax, dy = p2y[k1] - ay;
        float qx[8], qy[8];
        int m = 0;
        for (int i = 0; i < n; i++) {
            float sx = px[i], sy = py[i];
            int ei = (i + 1 == n) ? 0 : (i + 1);
            float ex = px[ei], ey = py[ei];
            float cs = dx * (sy - ay) - dy * (sx - ax);
            float ce = dx * (ey - ay) - dy * (ex - ax);
            float denom = cs - ce;
            float t = cs / ((fabsf(denom) > 1e-12f) ? denom : 1e-12f);
            float ipx = sx + t * (ex - sx);
            float ipy = sy + t * (ey - sy);
            bool s_in = (cs >= 0.0f), e_in = (ce >= 0.0f);
            if (s_in != e_in) { int mm = m < 7 ? m : 7; qx[mm] = ipx; qy[mm] = ipy; m++; }
            if (e_in)         { int mm = m < 7 ? m : 7; qx[mm] = ex;  qy[mm] = ey;  m++; }
        }
        if (m > 8) m = 8;
        n = m;
        for (int i = 0; i < n; i++) { px[i] = qx[i]; py[i] = qy[i]; }
    }
    if (n < 3) return 0.0f;
    float acc = 0.0f;
    for (int i = 0; i < n; i++) {
        int k2 = (i + 1 == n) ? 0 : (i + 1);
        acc += px[i] * py[k2] - px[k2] * py[i];
    }
    return 0.5f * fabsf(acc);
}

// ---------------- fused kernel: decode + sort + NMS, then last block topk ---
__global__ void k_fused(const float* __restrict__ logits,
                        const float* __restrict__ regr,
                        const float* __restrict__ rrects,
                        float* __restrict__ out)
{
    int g = blockIdx.x;                 // 0..39
    int b = g / (C-1);
    int cls = g % (C-1) + 1;
    int tid = threadIdx.x;              // 0..511
    int lane = tid & 31;
    int wid = tid >> 5;

    extern __shared__ float sm[];
    float* sv     = sm;                        // 512
    int*   si     = (int*)(sv + P);            // 512
    float* boxbuf = (float*)(si + P);          // 5*512 (SoA)
    float* ptsx   = boxbuf + 5 * P;            // 512*4
    float* ptsy   = ptsx + P * 4;              // 512*4
    float* bminx  = ptsy + P * 4;              // 512
    float* bminy  = bminx + P;
    float* bmaxx  = bminy + P;
    float* bmaxy  = bmaxx + P;
    float* areaS  = bmaxy + P;
    unsigned* sup = (unsigned*)(areaS + P);    // 512*16
    int* squeue   = (int*)(sup + P * 16);      // SQ_CAP
    __shared__ int qcnt;
    __shared__ unsigned keepM[16];
    __shared__ int Vsh;
    __shared__ int isLast;
    __shared__ int partial[2][32];
    __shared__ int ncand;
    __shared__ float cv[CANDCAP];
    __shared__ int   ci[CANDCAP];

    int row = b * P + tid;

    // ---- softmax score for (row, cls) ----
    const float* lg = &logits[row * C];
    float mx = lg[0];
    #pragma unroll
    for (int i = 1; i < C; i++) mx = fmaxf(mx, lg[i]);
    float ssum = 0.0f;
    float ecls = 0.0f;
    #pragma unroll
    for (int i = 0; i < C; i++) {
        float e = expf(lg[i] - mx);
        ssum += e;
        if (i == cls) ecls = e;
    }
    float s = ecls / ssum;
    float v = (s > SCORE_THRESH) ? s : -1.0f;
    int idx = tid;

    // ---- decode (row, cls) box into smem ----
    {
        float axc = rrects[row*5+0], ayc = rrects[row*5+1];
        float aw  = rrects[row*5+2], ah  = rrects[row*5+3];
        float aa  = rrects[row*5+4];
        const float* d = &regr[row * C * REG + cls * REG];
        float dx = d[0] / 10.0f;
        float dy = d[1] / 10.0f;
        float dw = fminf(d[2] / 5.0f, BBOX_CLIP);
        float dh = fminf(d[3] / 5.0f, BBOX_CLIP);
        float da = d[4] / 3.0f;
        boxbuf[0*P + tid] = dx * aw + axc;
        boxbuf[1*P + tid] = dy * ah + ayc;
        boxbuf[2*P + tid] = expf(dw) * aw;
        boxbuf[3*P + tid] = expf(dh) * ah;
        boxbuf[4*P + tid] = da * RAD2DEG + aa;
    }

    // ---- bitonic sort 512 by (score desc, idx asc) ----
    #pragma unroll
    for (int k = 2; k <= 32; k <<= 1) {
        bool dir = ((tid & k) == 0);
        #pragma unroll
        for (int j = k >> 1; j >= 1; j >>= 1) cmp_shfl(v, idx, tid, j, dir);
    }
    #pragma unroll
    for (int k = 64; k <= 512; k <<= 1) {
        bool dir = ((tid & k) == 0);
        #pragma unroll
        for (int j = k >> 1; j >= 32; j >>= 1) {
            sv[tid] = v; si[tid] = idx;
            __syncthreads();
            int p2 = tid ^ j;
            float ov = sv[p2]; int oi = si[p2];
            bool lower = ((tid & j) == 0);
            bool before = (v > ov) || (v == ov && idx < oi);
            bool lower_before = lower ? before : !before;
            if (lower_before != dir) { v = ov; idx = oi; }
            __syncthreads();
        }
        #pragma unroll
        for (int j = 16; j >= 1; j >>= 1) cmp_shfl(v, idx, tid, j, dir);
    }
    __syncthreads();

    // ---- gather decoded box of ranked proposal ----
    float pp[5];
    #pragma unroll
    for (int k = 0; k < 5; k++) {
        pp[k] = boxbuf[k*P + idx];
        g_pr_s[(g * P + tid) * 5 + k] = pp[k];
    }

    // ---- corner points + aabb + area ----
    float th = pp[4] * DEG2RAD;
    float cth = cosf(th), sth = sinf(th);
    float hx = pp[2] * 0.5f, hy = pp[3] * 0.5f;
    float oxs[4] = {-hx, hx, hx, -hx};
    float oys[4] = {-hy, -hy, hy, hy};
    float cxx[4], cyy[4];
    float mnx = 1e30f, mny = 1e30f, mxx = -1e30f, mxy = -1e30f;
    #pragma unroll
    for (int i = 0; i < 4; i++) {
        float cx = pp[0] + cth * oxs[i] - sth * oys[i];
        float cy = pp[1] + sth * oxs[i] + cth * oys[i];
        cxx[i] = cx; cyy[i] = cy;
        mnx = fminf(mnx, cx); mxx = fmaxf(mxx, cx);
        mny = fminf(mny, cy); mxy = fmaxf(mxy, cy);
    }
    g_bx_s[(g * P + tid) * 4 + 0] = fminf(fmaxf(mnx, 0.0f), IMW_M1);
    g_bx_s[(g * P + tid) * 4 + 1] = fminf(fmaxf(mny, 0.0f), IMH_M1);
    g_bx_s[(g * P + tid) * 4 + 2] = fminf(fmaxf(mxx, 0.0f), IMW_M1);
    g_bx_s[(g * P + tid) * 4 + 3] = fminf(fmaxf(mxy, 0.0f), IMH_M1);

    __syncthreads();

    #pragma unroll
    for (int i = 0; i < 4; i++) { ptsx[tid*4+i] = cxx[i]; ptsy[tid*4+i] = cyy[i]; }
    bminx[tid] = mnx; bmaxx[tid] = mxx;
    bminy[tid] = mny; bmaxy[tid] = mxy;
    areaS[tid] = pp[2] * pp[3];
    #pragma unroll
    for (int k = 0; k < 16; k++) sup[tid * 16 + k] = 0u;

    bool valid = v > SCORE_THRESH;
    int V = __syncthreads_count(valid);   // valid entries form a sorted prefix
    if (tid == 0) { qcnt = 0; Vsh = V; }
    __syncthreads();

    // ---- phase 1: AABB + IoU-upper-bound precheck -> pair queue ----
    long long M = (long long)V * (V - 1) / 2;
    if (M > 0) {
        int nIter = (int)((M + P - 1) / P);
        long long t = tid;
        int pi = 0, pj = 0;
        if (t < M) {
            pi = (int)((sqrtf(8.0f * (float)t + 1.0f) + 1.0f) * 0.5f);
            while ((long long)pi * (pi - 1) / 2 > t) pi--;
            while ((long long)(pi + 1) * pi / 2 <= t) pi++;
            pj = (int)(t - (long long)pi * (pi - 1) / 2);
        }
        for (int it = 0; it < nIter; it++) {
            bool push = false;
            if (t < M) {
                float iw = fminf(bmaxx[pi], bmaxx[pj]) - fmaxf(bminx[pi], bminx[pj]);
                float ih = fminf(bmaxy[pi], bmaxy[pj]) - fmaxf(bminy[pi], bminy[pj]);
                if (iw > 0.0f && ih > 0.0f) {
                    float ai = areaS[pi], aj = areaS[pj];
                    float ub = fminf(iw * ih, fminf(ai, aj));
                    float bound = ub / (ai + aj - ub + 1e-8f);
                    push = bound > NMS_THR * 0.999f;   // conservative upper bound
                }
            }
            unsigned mb = __ballot_sync(FULLM, push);
            if (mb) {
                int ldr = __ffs(mb) - 1;
                int basep = 0;
                if (lane == ldr) basep = atomicAdd(&qcnt, __popc(mb));
                basep = __shfl_sync(FULLM, basep, ldr);
                if (push) {
                    int pos = basep + __popc(mb & ((1u << lane) - 1u));
                    int enc = (pi << 16) | pj;
                    if (pos < SQ_CAP) squeue[pos] = enc;
                    else g_queue[g * QCAP + (pos - SQ_CAP)] = enc;
                }
            }
            // advance t by P with incremental (i,j) update
            t += P;
            if (t < M) {
                pj += P;
                while (pj >= pi) { pj -= pi; pi++; }
            }
        }
    }
    __syncthreads();

    // ---- phase 2: exact IoU over surviving pairs ----
    int nq = qcnt;
    for (int q = tid; q < nq; q += blockDim.x) {
        int ij = (q < SQ_CAP) ? squeue[q] : g_queue[g * QCAP + (q - SQ_CAP)];
        int i = ij >> 16, j = ij & 0xffff;
        float inter = inter_area(&ptsx[i * 4], &ptsy[i * 4], &ptsx[j * 4], &ptsy[j * 4]);
        float iou = inter / (areaS[i] + areaS[j] - inter + 1e-8f);
        if (iou > NMS_THR) atomicOr(&sup[i * 16 + (j >> 5)], 1u << (j & 31));
    }
    __syncthreads();

    // ---- phase 3: greedy scan (warp 0, prefetched) ----
    if (tid < 32) {
        unsigned kw = 0;
        int VV = Vsh;
        unsigned srow = (tid < 16 && VV > 0) ? sup[tid] : 0u;
        for (int i = 0; i < VV; i++) {
            unsigned nrow = (tid < 16 && (i + 1) < VV) ? sup[(i + 1) * 16 + tid] : 0u;
            bool any = __any_sync(FULLM, (kw & srow) != 0u);
            if (!any && tid == (i >> 5)) kw |= 1u << (i & 31);
            srow = nrow;
        }
        if (tid < 16) keepM[tid] = kw;
    }
    __syncthreads();

    bool kept = (tid < Vsh) && ((keepM[tid >> 5] >> (tid & 31)) & 1u);
    g_msk[g * P + tid] = kept ? v : -1.0f;

    // ================= last-block top-k =================
    __threadfence();
    __syncthreads();
    if (tid == 0) {
        unsigned old = atomicAdd(&g_done, 1u);
        isLast = (old == NGRP - 1);
        if (isLast) g_done = 0;      // reset for next launch
    }
    __syncthreads();
    if (!isLast) return;
    __threadfence();

    // zero unused partial lanes once
    if (tid >= 16 && tid < 32) { partial[0][tid] = 0; partial[1][tid] = 0; }

    for (int b2 = 0; b2 < B; b2++) {
        // load this image's masked scores into registers
        float vv[K4PER];
        unsigned key[K4PER];
        #pragma unroll
        for (int i = 0; i < K4PER; i++) {
            float x = g_msk[b2 * TOT + tid + i * P];
            vv[i] = x;
            unsigned bb = __float_as_uint(x);
            key[i] = bb ^ ((bb & 0x80000000u) ? 0xFFFFFFFFu : 0x80000000u);
        }
        if (tid == 0) ncand = 0;
        __syncthreads();

        // radix binary search with early exit (count in [DET, CANDCAP])
        unsigned cur = 0u;
        int curcnt = TOT;
        for (int bit = 31; bit >= 0; bit--) {
            unsigned trial = cur | (1u << bit);
            int c = 0;
            #pragma unroll
            for (int i = 0; i < K4PER; i++) c += (key[i] >= trial);
            #pragma unroll
            for (int o = 16; o; o >>= 1) c += __shfl_xor_sync(FULLM, c, o);
            if (lane == 0) partial[bit & 1][wid] = c;
            __syncthreads();
            int t2 = partial[bit & 1][lane];
            #pragma unroll
            for (int o = 16; o; o >>= 1) t2 += __shfl_xor_sync(FULLM, t2, o);
            if (t2 >= DET) { cur = trial; curcnt = t2; }
            if (curcnt <= CANDCAP) break;
        }
        unsigned kthr = cur;
        __syncthreads();

        // collect candidates (ballot-aggregated)
        #pragma unroll
        for (int i = 0; i < K4PER; i++) {
            bool cand = (key[i] >= kthr) && (vv[i] > 0.0f);
            unsigned mb = __ballot_sync(FULLM, cand);
            if (mb) {
                int ldr = __ffs(mb) - 1;
                int basep = 0;
                if (lane == ldr) basep = atomicAdd(&ncand, __popc(mb));
                basep = __shfl_sync(FULLM, basep, ldr);
                if (cand) {
                    int pos = basep + __popc(mb & ((1u << lane) - 1u));
                    if (pos < CANDCAP) { cv[pos] = vv[i]; ci[pos] = tid + i * P; }
                }
            }
        }
        __syncthreads();
        int nc = min(ncand, CANDCAP);

        // bitonic sort CANDCAP=256 (tid<256 hold elements)
        float mv = -1e30f; int mi = 0x7fffffff;
        if (tid < CANDCAP && tid < nc) { mv = cv[tid]; mi = ci[tid]; }
        __syncthreads();

        if (tid < CANDCAP) {
            #pragma unroll
            for (int k = 2; k <= 32; k <<= 1) {
                bool dir = ((tid & k) == 0);
                #pragma unroll
                for (int j = k >> 1; j >= 1; j >>= 1) cmp_shfl(mv, mi, tid, j, dir);
            }
        }
        #pragma unroll
        for (int k = 64; k <= CANDCAP; k <<= 1) {
            bool dir = ((tid & k) == 0);
            #pragma unroll
            for (int j = k >> 1; j >= 32; j >>= 1) {
                if (tid < CANDCAP) { cv[tid] = mv; ci[tid] = mi; }
                __syncthreads();
                if (tid < CANDCAP) {
                    int p2 = tid ^ j;
                    float ov = cv[p2]; int oi = ci[p2];
                    bool lower = ((tid & j) == 0);
                    bool before = (mv > ov) || (mv == ov && mi < oi);
                    bool lower_before = lower ? before : !before;
                    if (lower_before != dir) { mv = ov; mi = oi; }
                }
                __syncthreads();
            }
            if (tid < CANDCAP) {
                #pragma unroll
                for (int j = 16; j >= 1; j >>= 1) cmp_shfl(mv, mi, tid, j, dir);
            }
        }

        // output: bb [B,DET,4] | rr [B,DET,5] | sc [B,DET] | lab [B,DET]
        if (tid < DET) {
            float val = mv;
            int fi = (mi == 0x7fffffff) ? 0 : mi;
            bool ok = val > 0.0f;
            int cls2 = fi / P + 1;
            int gi = b2 * TOT + fi;
            int o = b2 * DET + tid;
            #pragma unroll
            for (int jj = 0; jj < 4; jj++)
                out[o * 4 + jj] = ok ? g_bx_s[gi * 4 + jj] : 0.0f;
            #pragma unroll
            for (int jj = 0; jj < 5; jj++)
                out[B * DET * 4 + o * 5 + jj] = ok ? g_pr_s[gi * 5 + jj] : 0.0f;
            out[B * DET * 9 + o] = ok ? val : 0.0f;
            out[B * DET * 10 + o] = ok ? (float)cls2 : 0.0f;
        }
        __syncthreads();   // cv/ci/ncand reuse safety for next image
    }
}

// ---------------- launch ----------------
extern "C" void kernel_launch(void* const* d_in, const int* in_sizes, int n_in,
                              void* d_out, int out_size)
{
    const float* logits = (const float*)d_in[0];
    const float* regr   = (const float*)d_in[1];
    const float* rrects = (const float*)d_in[2];
    float* out = (float*)d_out;

    const int SMEM = (P + 5*P + P*4*2 + 5*P) * (int)sizeof(float)
                   + P * (int)sizeof(int)
                   + P*16*(int)sizeof(unsigned) + SQ_CAP*(int)sizeof(int);
    cudaFuncSetAttribute(k_fused, cudaFuncAttributeMaxDynamicSharedMemorySize, SMEM);

    k_fused<<<NGRP, P, SMEM>>>(logits, regr, rrects, out);
}

// round 10
// speedup vs baseline: 1.2128x; 1.2128x over previous
#include <cuda_runtime.h>
#include <cuda_bf16.h>
#include <math.h>
#include <stdint.h>

#define B 2
#define P 512
#define C 21
#define REG 5
#define DET 100
#define NGRP (B*(C-1))          // 40
#define TOT ((C-1)*P)           // 10240 per image
#define SCORE_THRESH 0.05f
#define NMS_THR 0.5f
#define BBOX_CLIP 4.135166556742356f   // log(1000/16)
#define DEG2RAD 0.017453292519943295f
#define RAD2DEG 57.29577951308232f
#define IMW_M1 1023.0f
#define IMH_M1 799.0f
#define QCAP 131072
#define SQ_CAP 4096
#define FULLM 0xffffffffu
#define CANDCAP 256

// ---------------- device scratch ----------------
__device__ float g_pr_s[NGRP * P * 5];           // rank-ordered proposals
__device__ float g_bx_s[NGRP * P * 4];           // rank-ordered clipped aabb
__device__ float g_msk[B * (C-1) * P];           // post-NMS masked scores
__device__ int   g_queue[NGRP * QCAP];           // pair-queue overflow

// ---------------- bitonic helper (desc by value, asc by index) --------------
__device__ __forceinline__ void cmp_shfl(float& v, int& i, int tid, int j, bool dir)
{
    float ov = __shfl_xor_sync(FULLM, v, j);
    int   oi = __shfl_xor_sync(FULLM, i, j);
    bool lower = ((tid & j) == 0);
    bool before = (v > ov) || (v == ov && i < oi);
    bool lower_before = lower ? before : !before;
    if (lower_before != dir) { v = ov; i = oi; }
}

// ---------------- exact quad-quad intersection area (matches reference) -----
__device__ float inter_area(const float* __restrict__ p1x, const float* __restrict__ p1y,
                            const float* __restrict__ p2x, const float* __restrict__ p2y)
{
    float px[8], py[8];
    #pragma unroll
    for (int i = 0; i < 4; i++) { px[i] = p1x[i]; py[i] = p1y[i]; }
    int n = 4;

    for (int k = 0; k < 4; k++) {
        float ax = p2x[k], ay = p2y[k];
        int k1 = (k + 1) & 3;
        float dx = p2x[k1] - ax, dy = p2y[k1] - ay;
        float qx[8], qy[8];
        int m = 0;
        for (int i = 0; i < n; i++) {
            float sx = px[i], sy = py[i];
            int ei = (i + 1 == n) ? 0 : (i + 1);
            float ex = px[ei], ey = py[ei];
            float cs = dx * (sy - ay) - dy * (sx - ax);
            float ce = dx * (ey - ay) - dy * (ex - ax);
            float denom = cs - ce;
            float t = cs / ((fabsf(denom) > 1e-12f) ? denom : 1e-12f);
            float ipx = sx + t * (ex - sx);
            float ipy = sy + t * (ey - sy);
            bool s_in = (cs >= 0.0f), e_in = (ce >= 0.0f);
            if (s_in != e_in) { int mm = m < 7 ? m : 7; qx[mm] = ipx; qy[mm] = ipy; m++; }
            if (e_in)         { int mm = m < 7 ? m : 7; qx[mm] = ex;  qy[mm] = ey;  m++; }
        }
        if (m > 8) m = 8;
        n = m;
        for (int i = 0; i < n; i++) { px[i] = qx[i]; py[i] = qy[i]; }
    }
    if (n < 3) return 0.0f;
    float acc = 0.0f;
    for (int i = 0; i < n; i++) {
        int k2 = (i + 1 == n) ? 0 : (i + 1);
        acc += px[i] * py[k2] - px[k2] * py[i];
    }
    return 0.5f * fabsf(acc);
}

// ---------------- kernel: decode + rank + rotated NMS per group -------------
__global__ void k123_sortnms(const float* __restrict__ logits,
                             const float* __restrict__ regr,
                             const float* __restrict__ rrects)
{
    int g = blockIdx.x;                 // 0..39
    int b = g / (C-1);
    int cls = g % (C-1) + 1;
    int tid = threadIdx.x;              // 0..511
    int lane = tid & 31;

    extern __shared__ float4 smf4[];
    float4* sbb  = smf4;                        // 512 float4 (mnx,mny,mxx,mxy)
    float*  cs   = (float*)(sbb + P);           // 512 compacted scores
    int*    cidx = (int*)(cs + P);              // 512 compacted orig idx
    float*  ptsx = (float*)(cidx + P);          // 512*4
    float*  ptsy = ptsx + 4 * P;                // 512*4
    float*  areaS= ptsy + 4 * P;                // 512
    unsigned* sup = (unsigned*)(areaS + P);     // 512*16
    int* squeue  = (int*)(sup + 16 * P);        // SQ_CAP
    __shared__ int vcnt, icnt, qcnt, Vsh;
    __shared__ unsigned dirty[16];
    __shared__ unsigned keepM[16];

    int row = b * P + tid;

    // ---- softmax score for (row, cls) ----
    const float* lg = &logits[row * C];
    float mx = lg[0];
    #pragma unroll
    for (int i = 1; i < C; i++) mx = fmaxf(mx, lg[i]);
    float ssum = 0.0f, ecls = 0.0f;
    #pragma unroll
    for (int i = 0; i < C; i++) {
        float e = expf(lg[i] - mx);
        ssum += e;
        if (i == cls) ecls = e;
    }
    float s = ecls / ssum;
    bool valid = s > SCORE_THRESH;

    // ---- decode own (row, cls) box into registers ----
    float pp[5];
    {
        float axc = rrects[row*5+0], ayc = rrects[row*5+1];
        float aw  = rrects[row*5+2], ah  = rrects[row*5+3];
        float aa  = rrects[row*5+4];
        const float* d = &regr[row * C * REG + cls * REG];
        float dx = d[0] / 10.0f;
        float dy = d[1] / 10.0f;
        float dw = fminf(d[2] / 5.0f, BBOX_CLIP);
        float dh = fminf(d[3] / 5.0f, BBOX_CLIP);
        float da = d[4] / 3.0f;
        pp[0] = dx * aw + axc;
        pp[1] = dy * ah + ayc;
        pp[2] = expf(dw) * aw;
        pp[3] = expf(dh) * ah;
        pp[4] = da * RAD2DEG + aa;
    }

    // ---- corners + aabb (registers) ----
    float th = pp[4] * DEG2RAD;
    float cth = cosf(th), sth = sinf(th);
    float hx = pp[2] * 0.5f, hy = pp[3] * 0.5f;
    float oxs[4] = {-hx, hx, hx, -hx};
    float oys[4] = {-hy, -hy, hy, hy};
    float cxx[4], cyy[4];
    float mnx = 1e30f, mny = 1e30f, mxx = -1e30f, mxy = -1e30f;
    #pragma unroll
    for (int i = 0; i < 4; i++) {
        float cx = pp[0] + cth * oxs[i] - sth * oys[i];
        float cy = pp[1] + sth * oxs[i] + cth * oys[i];
        cxx[i] = cx; cyy[i] = cy;
        mnx = fminf(mnx, cx); mxx = fmaxf(mxx, cx);
        mny = fminf(mny, cy); mxy = fmaxf(mxy, cy);
    }

    // ---- init shared ----
    if (tid == 0) { vcnt = 0; icnt = 0; qcnt = 0; }
    if (tid < 16) dirty[tid] = 0u;
    #pragma unroll
    for (int k = 0; k < 16; k++) sup[k * P + tid] = 0u;
    __syncthreads();

    // ---- compact valid entries ----
    unsigned mbv = __ballot_sync(FULLM, valid);
    int wb = 0;
    if (lane == 0 && mbv) wb = atomicAdd(&vcnt, __popc(mbv));
    wb = __shfl_sync(FULLM, wb, 0);
    if (valid) {
        int p = wb + __popc(mbv & ((1u << lane) - 1u));
        cs[p] = s; cidx[p] = tid;
    }
    unsigned mbi = __ballot_sync(FULLM, !valid);
    int ib = 0;
    if (lane == 0 && mbi) ib = atomicAdd(&icnt, __popc(mbi));
    ib = __shfl_sync(FULLM, ib, 0);
    int irank = (!valid) ? (ib + __popc(mbi & ((1u << lane) - 1u))) : -1;
    __syncthreads();
    int V = vcnt;
    if (tid == 0) Vsh = V;

    // ---- rank valid entries by (score desc, idx asc); scatter own data ----
    int rank = -1;
    if (valid) {
        int r = 0;
        #pragma unroll 4
        for (int i = 0; i < V; i++) {
            float o = cs[i];
            r += (o > s) || (o == s && cidx[i] < tid);
        }
        rank = r;
        #pragma unroll
        for (int i = 0; i < 4; i++) { ptsx[rank*4+i] = cxx[i]; ptsy[rank*4+i] = cyy[i]; }
        sbb[rank] = make_float4(mnx, mny, mxx, mxy);
        areaS[rank] = pp[2] * pp[3];
        #pragma unroll
        for (int k = 0; k < 5; k++) g_pr_s[(g * P + rank) * 5 + k] = pp[k];
        g_bx_s[(g * P + rank) * 4 + 0] = fminf(fmaxf(mnx, 0.0f), IMW_M1);
        g_bx_s[(g * P + rank) * 4 + 1] = fminf(fmaxf(mny, 0.0f), IMH_M1);
        g_bx_s[(g * P + rank) * 4 + 2] = fminf(fmaxf(mxx, 0.0f), IMW_M1);
        g_bx_s[(g * P + rank) * 4 + 3] = fminf(fmaxf(mxy, 0.0f), IMH_M1);
    } else {
        g_msk[g * P + V + irank] = -1.0f;   // positions >= V: never selected
    }
    __syncthreads();

    // ---- phase 1: AABB + IoU-upper-bound precheck -> pair queue ----
    long long M = (long long)V * (V - 1) / 2;
    if (M > 0) {
        int nIter = (int)((M + P - 1) / P);
        long long t = tid;
        int pi = 0, pj = 0;
        if (t < M) {
            pi = (int)((sqrtf(8.0f * (float)t + 1.0f) + 1.0f) * 0.5f);
            while ((long long)pi * (pi - 1) / 2 > t) pi--;
            while ((long long)(pi + 1) * pi / 2 <= t) pi++;
            pj = (int)(t - (long long)pi * (pi - 1) / 2);
        }
        for (int it = 0; it < nIter; it++) {
            bool push = false;
            if (t < M) {
                float4 bi = sbb[pi], bj = sbb[pj];
                float iw = fminf(bi.z, bj.z) - fmaxf(bi.x, bj.x);
                float ih = fminf(bi.w, bj.w) - fmaxf(bi.y, bj.y);
                if (iw > 0.0f && ih > 0.0f) {
                    float ai = areaS[pi], aj = areaS[pj];
                    float ub = fminf(iw * ih, fminf(ai, aj));
                    float bound = ub / (ai + aj - ub + 1e-8f);
                    push = bound > NMS_THR * 0.999f;   // conservative upper bound
                }
            }
            unsigned mb = __ballot_sync(FULLM, push);
            if (mb) {
                int ldr = __ffs(mb) - 1;
                int basep = 0;
                if (lane == ldr) basep = atomicAdd(&qcnt, __popc(mb));
                basep = __shfl_sync(FULLM, basep, ldr);
                if (push) {
                    int pos = basep + __popc(mb & ((1u << lane) - 1u));
                    int enc = (pi << 16) | pj;
                    if (pos < SQ_CAP) squeue[pos] = enc;
                    else g_queue[g * QCAP + (pos - SQ_CAP)] = enc;
                }
            }
            t += P;
            if (t < M) {
                pj += P;
                while (pj >= pi) { pj -= pi; pi++; }
            }
        }
    }
    __syncthreads();

    // ---- phase 2: exact IoU over surviving pairs ----
    int nq = qcnt;
    for (int q = tid; q < nq; q += blockDim.x) {
        int ij = (q < SQ_CAP) ? squeue[q] : g_queue[g * QCAP + (q - SQ_CAP)];
        int i = ij >> 16, j = ij & 0xffff;
        float inter = inter_area(&ptsx[i * 4], &ptsy[i * 4], &ptsx[j * 4], &ptsy[j * 4]);
        float iou = inter / (areaS[i] + areaS[j] - inter + 1e-8f);
        if (iou > NMS_THR) {
            atomicOr(&sup[i * 16 + (j >> 5)], 1u << (j & 31));
            atomicOr(&dirty[i >> 5], 1u << (i & 31));
        }
    }
    __syncthreads();

    // ---- phase 3: sparse greedy scan (warp 0, only dirty rows) ----
    if (tid < 32) {
        unsigned km = 0u;
        if (tid < 16) {
            int lo = tid * 32;
            int VV = Vsh;
            km = (VV >= lo + 32) ? 0xffffffffu : (VV > lo ? ((1u << (VV - lo)) - 1u) : 0u);
        }
        #pragma unroll
        for (int w = 0; w < 16; w++) {
            unsigned m = dirty[w];
            while (m) {
                int i = w * 32 + __ffs(m) - 1;
                m &= m - 1;
                unsigned srow = (tid < 16) ? sup[i * 16 + tid] : 0u;
                bool any = __any_sync(FULLM, (srow & km) != 0u);
                if (any && tid == (i >> 5)) km &= ~(1u << (i & 31));
            }
        }
        if (tid < 16) keepM[tid] = km;
    }
    __syncthreads();

    if (valid) {
        bool kept = (keepM[rank >> 5] >> (rank & 31)) & 1u;
        g_msk[g * P + rank] = kept ? s : -1.0f;
    }
}

// ---------------- kernel 4: radix-threshold top-100 + output ----------------
#define K4_THREADS 1024
#define K4_PER (TOT / K4_THREADS)   // 10 (exact)

__global__ void k4_topk(float* __restrict__ out)
{
    int b = blockIdx.x;
    int tid = threadIdx.x;
    int lane = tid & 31;
    int wid = tid >> 5;

    float v[K4_PER];
    unsigned key[K4_PER];
    #pragma unroll
    for (int i = 0; i < K4_PER; i++) {
        float x = g_msk[b * TOT + tid + i * K4_THREADS];
        v[i] = x;
        unsigned bb = __float_as_uint(x);
        key[i] = bb ^ ((bb & 0x80000000u) ? 0xFFFFFFFFu : 0x80000000u);
    }

    __shared__ int partial[2][32];
    __shared__ int ncand;
    __shared__ float cv[CANDCAP];
    __shared__ int   ci[CANDCAP];

    if (tid == 0) ncand = 0;

    // prepass: count positives (== count key >= 0x80000000); scores in (0,1)
    // means bits 31/30 of the radix search resolve analytically.
    unsigned cur = 0x80000000u;
    int curcnt;
    {
        int c = 0;
        #pragma unroll
        for (int i = 0; i < K4_PER; i++) c += (key[i] >= cur);
        c = __reduce_add_sync(FULLM, c);
        if (lane == 0) partial[0][wid] = c;
        __syncthreads();
        curcnt = __reduce_add_sync(FULLM, partial[0][lane]);
    }

    if (curcnt > CANDCAP) {
        for (int bit = 29; bit >= 0; bit--) {
            unsigned trial = cur | (1u << bit);
            int c = 0;
            #pragma unroll
            for (int i = 0; i < K4_PER; i++) c += (key[i] >= trial);
            c = __reduce_add_sync(FULLM, c);
            if (lane == 0) partial[bit & 1][wid] = c;
            __syncthreads();
            int t2 = __reduce_add_sync(FULLM, partial[bit & 1][lane]);
            if (t2 >= DET) { cur = trial; curcnt = t2; }
            if (curcnt <= CANDCAP) break;
        }
    }
    unsigned kthr = cur;
    __syncthreads();

    // collect candidates (ballot-aggregated): key >= kthr AND positive value
    #pragma unroll
    for (int i = 0; i < K4_PER; i++) {
        bool cand = (key[i] >= kthr) && (v[i] > 0.0f);
        unsigned mb = __ballot_sync(FULLM, cand);
        if (mb) {
            int ldr = __ffs(mb) - 1;
            int basep = 0;
            if (lane == ldr) basep = atomicAdd(&ncand, __popc(mb));
            basep = __shfl_sync(FULLM, basep, ldr);
            if (cand) {
                int pos = basep + __popc(mb & ((1u << lane) - 1u));
                if (pos < CANDCAP) { cv[pos] = v[i]; ci[pos] = tid + i * K4_THREADS; }
            }
        }
    }
    __syncthreads();
    int nc = min(ncand, CANDCAP);

    // bitonic sort CANDCAP=256 candidates (regs + shfl; smem for j>=32)
    float mv = -1e30f; int mi = 0x7fffffff;
    if (tid < CANDCAP && tid < nc) { mv = cv[tid]; mi = ci[tid]; }
    __syncthreads();

    if (tid < CANDCAP) {
        #pragma unroll
        for (int k = 2; k <= 32; k <<= 1) {
            bool dir = ((tid & k) == 0);
            #pragma unroll
            for (int j = k >> 1; j >= 1; j >>= 1) cmp_shfl(mv, mi, tid, j, dir);
        }
    }
    #pragma unroll
    for (int k = 64; k <= CANDCAP; k <<= 1) {
        bool dir = ((tid & k) == 0);
        #pragma unroll
        for (int j = k >> 1; j >= 32; j >>= 1) {
            if (tid < CANDCAP) { cv[tid] = mv; ci[tid] = mi; }
            __syncthreads();
            if (tid < CANDCAP) {
                int p2 = tid ^ j;
                float ov = cv[p2]; int oi = ci[p2];
                bool lower = ((tid & j) == 0);
                bool before = (mv > ov) || (mv == ov && mi < oi);
                bool lower_before = lower ? before : !before;
                if (lower_before != dir) { mv = ov; mi = oi; }
            }
            __syncthreads();
        }
        if (tid < CANDCAP) {
            #pragma unroll
            for (int j = 16; j >= 1; j >>= 1) cmp_shfl(mv, mi, tid, j, dir);
        }
    }

    // output layout (float32): bb [B,DET,4] | rr [B,DET,5] | sc [B,DET] | lab [B,DET]
    if (tid < DET) {
        float val = mv;
        int fi = (mi == 0x7fffffff) ? 0 : mi;
        bool ok = val > 0.0f;
        int cls = fi / P + 1;
        int gi = b * TOT + fi;
        int o = b * DET + tid;
        #pragma unroll
        for (int jj = 0; jj < 4; jj++)
            out[o * 4 + jj] = ok ? g_bx_s[gi * 4 + jj] : 0.0f;
        #pragma unroll
        for (int jj = 0; jj < 5; jj++)
            out[B * DET * 4 + o * 5 + jj] = ok ? g_pr_s[gi * 5 + jj] : 0.0f;
        out[B * DET * 9 + o] = ok ? val : 0.0f;
        out[B * DET * 10 + o] = ok ? (float)cls : 0.0f;
    }
}

// ---------------- launch ----------------
extern "C" void kernel_launch(void* const* d_in, const int* in_sizes, int n_in,
                              void* d_out, int out_size)
{
    const float* logits = (const float*)d_in[0];
    const float* regr   = (const float*)d_in[1];
    const float* rrects = (const float*)d_in[2];
    float* out = (float*)d_out;

    const int SMEM = P * (int)sizeof(float4)                 // sbb
                   + P * (int)sizeof(float)                  // cs
                   + P * (int)sizeof(int)                    // cidx
                   + 8 * P * (int)sizeof(float)              // ptsx+ptsy
                   + P * (int)sizeof(float)                  // areaS
                   + 16 * P * (int)sizeof(unsigned)          // sup
                   + SQ_CAP * (int)sizeof(int);              // squeue
    cudaFuncSetAttribute(k123_sortnms, cudaFuncAttributeMaxDynamicSharedMemorySize, SMEM);

    k123_sortnms<<<NGRP, P, SMEM>>>(logits, regr, rrects);
    k4_topk<<<B, K4_THREADS>>>(out);
}